// round 12
// baseline (speedup 1.0000x reference)
#include <cuda_runtime.h>
#include <cuda_bf16.h>
#include <cstdint>
#include <math.h>

// ---------------- problem constants ----------------
#define PB   8
#define PNC  64
#define PN   128
#define PDN  64
#define PALPHA 2
#define PHMOD 64
#define PMOD_IN  133
#define PMOD_OUT 16512   // N*N + N

#define ROWS_TOTAL (PB*PNC*PN)        // 65536
#define CELLS      (PB*PNC)           // 512
#define WSPLIT_BLOCKS 225             // ceil(57344/256)

typedef unsigned long long u64;

// ---------------- scratch (device globals; no runtime alloc) ----------------
__device__ uint32_t g_x1h[ROWS_TOTAL*96];   // state-MLP input  [65536 x 192]
__device__ uint32_t g_x1l[ROWS_TOTAL*96];
__device__ uint32_t g_x2h[ROWS_TOTAL*64];   // msg-MLP input    [65536 x 128]
__device__ uint32_t g_x2l[ROWS_TOTAL*64];
__device__ uint32_t g_hidh[ROWS_TOTAL*128]; // hidden           [65536 x 256]
__device__ uint32_t g_hidl[ROWS_TOTAL*128];
__device__ uint32_t g_w1sh[256*96],  g_w1sl[256*96];    // state_w1 [256x192]
__device__ uint32_t g_w2sh[64*128],  g_w2sl[64*128];    // state_w2 [64x256]
__device__ uint32_t g_w1mh[256*64],  g_w1ml[256*64];    // msg_w1   [256x128]
__device__ uint32_t g_w2mh[64*128],  g_w2ml[64*128];    // msg_w2   [64x256]

__device__ float g_wstats[CELLS];
__device__ float g_hmean[CELLS*PDN];
__device__ float g_msgmean[CELLS*PDN];

// ---------------- helpers ----------------
__device__ __forceinline__ uint32_t smem_to_u32(const void* p) {
    uint32_t a;
    asm("{ .reg .u64 t; cvta.to.shared.u64 t, %1; cvt.u32.u64 %0, t; }"
        : "=r"(a) : "l"(p));
    return a;
}
__device__ __forceinline__ void splitp(float v0, float v1, uint32_t& hi, uint32_t& lo) {
    __nv_bfloat16 h0 = __float2bfloat16(v0), h1 = __float2bfloat16(v1);
    float r0 = v0 - __bfloat162float(h0), r1 = v1 - __bfloat162float(h1);
    __nv_bfloat16 l0 = __float2bfloat16(r0), l1 = __float2bfloat16(r1);
    hi = (uint32_t)__bfloat16_as_ushort(h0) | ((uint32_t)__bfloat16_as_ushort(h1) << 16);
    lo = (uint32_t)__bfloat16_as_ushort(l0) | ((uint32_t)__bfloat16_as_ushort(l1) << 16);
}
// per-64-col-chunk swizzled layout: row stride 128B, 16B granule xor
__device__ __forceinline__ uint32_t coff(int r, int k) {
    return (uint32_t)((r << 7) + ((((k >> 3) & 7) ^ (r & 7)) << 4) + ((k & 7) << 1));
}
__device__ __forceinline__ void ldsm4(uint32_t r[4], uint32_t a) {
    asm volatile("ldmatrix.sync.aligned.m8n8.x4.shared.b16 {%0,%1,%2,%3}, [%4];"
        : "=r"(r[0]), "=r"(r[1]), "=r"(r[2]), "=r"(r[3]) : "r"(a));
}
__device__ __forceinline__ void mma16816(float* c, const uint32_t* a, const uint32_t* b) {
    asm volatile("mma.sync.aligned.m16n8k16.row.col.f32.bf16.bf16.f32 "
        "{%0,%1,%2,%3}, {%4,%5,%6,%7}, {%8,%9}, {%0,%1,%2,%3};"
        : "+f"(c[0]), "+f"(c[1]), "+f"(c[2]), "+f"(c[3])
        : "r"(a[0]), "r"(a[1]), "r"(a[2]), "r"(a[3]), "r"(b[0]), "r"(b[1]));
}
#define CP16(dst, src) \
    asm volatile("cp.async.cg.shared.global [%0], [%1], 16;" :: "r"(dst), "l"(src))
#define CP16P(dst, src, pol) \
    asm volatile("cp.async.cg.shared.global.L2::cache_hint [%0], [%1], 16, %2;" \
                 :: "r"(dst), "l"(src), "l"(pol))
#define CP_COMMIT() asm volatile("cp.async.commit_group;" ::: "memory")
#define CP_WAIT1()  asm volatile("cp.async.wait_group 1;" ::: "memory")

// f32x2 packed fma
__device__ __forceinline__ u64 pk2(float a, float b) {
    u64 r;
    asm("mov.b64 %0, {%1,%2};" : "=l"(r)
        : "r"(__float_as_uint(a)), "r"(__float_as_uint(b)));
    return r;
}
__device__ __forceinline__ void upk2(u64 v, float& a, float& b) {
    unsigned int x, y;
    asm("mov.b64 {%0,%1}, %2;" : "=r"(x), "=r"(y) : "l"(v));
    a = __uint_as_float(x); b = __uint_as_float(y);
}
__device__ __forceinline__ void fma2(u64& d, u64 a, u64 b) {
    asm("fma.rn.f32x2 %0, %1, %2, %0;" : "+l"(d) : "l"(a), "l"(b));
}

// =====================================================================
// K1: blocks [0,512): received = W @ msg (+ inject, + mean|W|) -> split ops
//     blocks [512,737): weight split prep (merged wsplit)
// =====================================================================
__global__ void __launch_bounds__(256)
recv_kernel(const float* __restrict__ W,
            const float* __restrict__ msg,
            const float* __restrict__ h,
            const float* __restrict__ nid,
            const float* __restrict__ Haug,
            const float* __restrict__ injW,
            const float* __restrict__ injB,
            const float* __restrict__ sw1,
            const float* __restrict__ sw2,
            const float* __restrict__ mw1,
            const float* __restrict__ mw2)
{
    const int tid = threadIdx.x;

    if (blockIdx.x >= CELLS) {
        // ---- weight split part ----
        const int p = (blockIdx.x - CELLS) * 256 + tid;
        const float2* src; uint32_t *dh, *dl; int lp;
        if (p < 24576)      { src = (const float2*)sw1; dh = g_w1sh; dl = g_w1sl; lp = p; }
        else if (p < 32768) { src = (const float2*)sw2; dh = g_w2sh; dl = g_w2sl; lp = p - 24576; }
        else if (p < 49152) { src = (const float2*)mw1; dh = g_w1mh; dl = g_w1ml; lp = p - 32768; }
        else if (p < 57344) { src = (const float2*)mw2; dh = g_w2mh; dl = g_w2ml; lp = p - 49152; }
        else return;
        float2 v = src[lp];
        uint32_t hi, lo; splitp(v.x, v.y, hi, lo);
        dh[lp] = hi; dl[lp] = lo;
        return;
    }

    extern __shared__ float sm[];
    float* Ws  = sm;                      // 128*129
    float* Ms  = Ws + 128*129;            // 128*68
    float* cs  = Ms + 128*68;             // 64
    float* inj = cs + 64;                 // 128
    float* red = inj + 128;               // 8

    const int bc  = blockIdx.x;
    const int b   = bc >> 6;
    const int c   = bc & 63;

    const size_t wbase = (size_t)bc * (PN*PN);
    const size_t mbase = (size_t)bc * (PN*PDN);

    float wsum = 0.f;
    for (int idx = tid; idx < PN*PN; idx += 256) {
        int i = idx >> 7, j = idx & 127;
        float v = W[wbase + idx];
        Ws[i*129 + j] = v;
        wsum += fabsf(v);
    }
    for (int idx = tid; idx < PN*PDN; idx += 256) {
        int j = idx >> 6, d = idx & 63;
        Ms[j*68 + d] = msg[mbase + idx];
    }
    if (tid < PDN) cs[tid] = Haug[(size_t)b*(PNC*PDN) + c*PDN + tid];

    #pragma unroll
    for (int off = 16; off; off >>= 1)
        wsum += __shfl_down_sync(0xffffffffu, wsum, off);
    if ((tid & 31) == 0) red[tid >> 5] = wsum;
    __syncthreads();
    if (tid == 0) {
        float s = 0.f;
        #pragma unroll
        for (int w = 0; w < 8; w++) s += red[w];
        g_wstats[bc] = s * (1.f / 16384.f);
    }

    if (tid < PALPHA*PDN) {
        int o = tid;
        float a = injB[c*(PALPHA*PDN) + o];
        const float* iw = injW + ((size_t)c*(PALPHA*PDN) + o)*PDN;
        #pragma unroll 8
        for (int i = 0; i < PDN; i++) a += cs[i] * iw[i];
        inj[o] = a;
    }

    // split h -> X1[:,0:64], nid -> X1[:,128:192]
    for (int t = tid; t < 128*32; t += 256) {
        int r = t >> 5, p = t & 31;
        int gr = bc*128 + r;
        float2 hv = ((const float2*)(h + ((size_t)bc*128 + r)*64))[p];
        uint32_t hi, lo; splitp(hv.x, hv.y, hi, lo);
        g_x1h[(size_t)gr*96 + p] = hi;  g_x1l[(size_t)gr*96 + p] = lo;
        float2 nv = ((const float2*)(nid + ((size_t)c*128 + r)*64))[p];
        splitp(nv.x, nv.y, hi, lo);
        g_x1h[(size_t)gr*96 + 64 + p] = hi;  g_x1l[(size_t)gr*96 + 64 + p] = lo;
    }
    __syncthreads();

    const int rp = tid >> 2;
    const int d0 = (tid & 3) * 16;
    const int i0 = 2*rp, i1 = 2*rp + 1;

    u64 a0[8], a1[8];
    #pragma unroll
    for (int q = 0; q < 8; q++) { a0[q] = 0ull; a1[q] = 0ull; }

    const float* wr0 = Ws + i0*129;
    const float* wr1 = Ws + i1*129;
    #pragma unroll 2
    for (int j = 0; j < PN; j++) {
        float w0 = wr0[j];
        float w1v = wr1[j];
        u64 wp0 = pk2(w0, w0);
        u64 wp1 = pk2(w1v, w1v);
        const u64* mp = (const u64*)(Ms + j*68 + d0);
        #pragma unroll
        for (int q = 0; q < 8; q++) {
            u64 m = mp[q];
            fma2(a0[q], m, wp0);
            fma2(a1[q], m, wp1);
        }
    }

    const int gr0 = bc*128 + i0, gr1 = bc*128 + i1;
    const int pq = d0 >> 1;
    #pragma unroll
    for (int q = 0; q < 8; q++) {
        float x, y; upk2(a0[q], x, y);
        if (rp == 0) { x += inj[d0 + 2*q]; y += inj[d0 + 2*q + 1]; }
        uint32_t hi, lo; splitp(x, y, hi, lo);
        g_x1h[(size_t)gr0*96 + 32 + pq + q] = hi;  g_x1l[(size_t)gr0*96 + 32 + pq + q] = lo;
        g_x2h[(size_t)gr0*64 + 32 + pq + q] = hi;  g_x2l[(size_t)gr0*64 + 32 + pq + q] = lo;
        upk2(a1[q], x, y);
        if (rp == 0) { x += inj[64 + d0 + 2*q]; y += inj[64 + d0 + 2*q + 1]; }
        splitp(x, y, hi, lo);
        g_x1h[(size_t)gr1*96 + 32 + pq + q] = hi;  g_x1l[(size_t)gr1*96 + 32 + pq + q] = lo;
        g_x2h[(size_t)gr1*64 + 32 + pq + q] = hi;  g_x2l[(size_t)gr1*64 + 32 + pq + q] = lo;
    }
}

// =====================================================================
// Pipelined GEMM: C[MT x NT] = A[MT x K] @ B[NT x K]^T, split bf16 (3-pass),
// KC=64 chunks, 2-stage cp.async double buffer. 256 threads, 8 warps as
// (MT/32) M x (8/(MT/32)) N.  Grid: x = n-chunk (fast; A L2-reuse), y = rows.
// A-operand reads use L2::evict_first (read-once streams).
// =====================================================================
template<int MT, int K, int NT, int EPI, int ASRC, int BSRC>
__global__ void __launch_bounds__(256)
gemm_kernel(const float* __restrict__ bias, float* __restrict__ outF)
{
    constexpr int KP    = K / 2;        // u32 per row (global)
    constexpr int NC    = K / 64;       // k-chunks
    constexpr int ABYT  = MT * 256;     // A hi+lo bytes per stage
    constexpr int BBYT  = NT * 256;     // B hi+lo bytes per stage
    constexpr int STAGE = ABYT + BBYT;
    constexpr int WM    = MT / 32;      // warps along M
    constexpr int WN    = 8 / WM;       // warps along N
    constexpr int NTW   = NT / WN;      // cols per warp
    constexpr int NJ    = NTW / 8;
    constexpr int NPF   = NTW / 16;

    extern __shared__ unsigned char smx[];
    float* sBias  = (float*)(smx + 2*STAGE);
    float* colsum = sBias + NT;

    const uint32_t *Ahi, *Alo, *Bhi, *Blo;
    if      (ASRC == 0) { Ahi = g_x1h;  Alo = g_x1l; }
    else if (ASRC == 1) { Ahi = g_x2h;  Alo = g_x2l; }
    else                { Ahi = g_hidh; Alo = g_hidl; }
    if      (BSRC == 0) { Bhi = g_w1sh; Blo = g_w1sl; }
    else if (BSRC == 1) { Bhi = g_w2sh; Blo = g_w2sl; }
    else if (BSRC == 2) { Bhi = g_w1mh; Blo = g_w1ml; }
    else                { Bhi = g_w2mh; Blo = g_w2ml; }

    const int tid  = threadIdx.x;
    const int lane = tid & 31;
    const int wid  = tid >> 5;
    const int wm   = wid % WM;
    const int wn   = wid / WM;
    const int r0   = blockIdx.y * MT;
    const int n0   = blockIdx.x * NT;
    const uint32_t sb = smem_to_u32(smx);

    u64 pol;
    asm("createpolicy.fractional.L2::evict_first.b64 %0, 1.0;" : "=l"(pol));

    auto load_stage = [&](int s, int chunk) {
        const uint32_t base = sb + s*STAGE;
        const int kc = chunk * 32;                  // u32 offset into row
        for (int t = tid; t < MT*8; t += 256) {     // A: MT rows x 8 granules
            int r = t >> 3, g = t & 7;
            uint32_t d = base + (r << 7) + ((uint32_t)(g ^ (r & 7)) << 4);
            CP16P(d,            Ahi + (size_t)(r0 + r)*KP + kc + g*4, pol);
            CP16P(d + MT*128,   Alo + (size_t)(r0 + r)*KP + kc + g*4, pol);
        }
        for (int t = tid; t < NT*8; t += 256) {     // B: NT rows x 8 granules
            int r = t >> 3, g = t & 7;
            uint32_t d = base + ABYT + (r << 7) + ((uint32_t)(g ^ (r & 7)) << 4);
            CP16(d,            Bhi + (size_t)(n0 + r)*KP + kc + g*4);
            CP16(d + NT*128,   Blo + (size_t)(n0 + r)*KP + kc + g*4);
        }
    };

    load_stage(0, 0);
    CP_COMMIT();
    for (int t = tid; t < NT; t += 256) sBias[t] = bias[n0 + t];

    const int a_r = wm*32 + ((lane >> 3) & 1)*8 + (lane & 7);
    const int a_k = (lane >> 4) * 8;
    const int b_n = wn*NTW + (lane >> 4)*8 + (lane & 7);
    const int b_k = ((lane >> 3) & 1) * 8;

    float acc[2][NJ][4];
    #pragma unroll
    for (int mi = 0; mi < 2; mi++)
        #pragma unroll
        for (int nj = 0; nj < NJ; nj++)
            #pragma unroll
            for (int q = 0; q < 4; q++) acc[mi][nj][q] = 0.f;

    #pragma unroll 1
    for (int c = 0; c < NC; c++) {
        if (c + 1 < NC) load_stage((c + 1) & 1, c + 1);
        CP_COMMIT();
        CP_WAIT1();
        __syncthreads();

        const uint32_t st = sb + (c & 1)*STAGE;
        #pragma unroll
        for (int ks = 0; ks < 4; ks++) {
            const int k0 = ks * 16;
            uint32_t ah[2][4], al[2][4], bh[NPF][4], bl[NPF][4];
            #pragma unroll
            for (int mi = 0; mi < 2; mi++) {
                uint32_t o = coff(a_r + mi*16, k0 + a_k);
                ldsm4(ah[mi], st + o);
                ldsm4(al[mi], st + MT*128 + o);
            }
            #pragma unroll
            for (int np = 0; np < NPF; np++) {
                uint32_t o = coff(b_n + np*16, k0 + b_k);
                ldsm4(bh[np], st + ABYT + o);
                ldsm4(bl[np], st + ABYT + NT*128 + o);
            }
            #pragma unroll
            for (int mi = 0; mi < 2; mi++)
                #pragma unroll
                for (int nj = 0; nj < NJ; nj++) {
                    const uint32_t* bph = &bh[nj >> 1][(nj & 1)*2];
                    const uint32_t* bpl = &bl[nj >> 1][(nj & 1)*2];
                    mma16816(acc[mi][nj], ah[mi], bph);
                    mma16816(acc[mi][nj], ah[mi], bpl);
                    mma16816(acc[mi][nj], al[mi], bph);
                }
        }
        __syncthreads();
    }

    // ---- epilogue ----
    const int g  = lane >> 2;
    const int cq = lane & 3;

    if (EPI == 0) {
        #pragma unroll
        for (int mi = 0; mi < 2; mi++) {
            const int row = wm*32 + mi*16 + g;
            const int gr  = r0 + row;
            #pragma unroll
            for (int nj = 0; nj < NJ; nj++) {
                const int colL = wn*NTW + nj*8 + cq*2;
                const int col  = n0 + colL;
                float b0 = sBias[colL], b1 = sBias[colL + 1];
                float v0 = tanhf(acc[mi][nj][0] + b0);
                float v1 = tanhf(acc[mi][nj][1] + b1);
                float v2 = tanhf(acc[mi][nj][2] + b0);
                float v3 = tanhf(acc[mi][nj][3] + b1);
                uint32_t hi, lo;
                splitp(v0, v1, hi, lo);
                g_hidh[(size_t)gr*128 + (col >> 1)] = hi;
                g_hidl[(size_t)gr*128 + (col >> 1)] = lo;
                splitp(v2, v3, hi, lo);
                g_hidh[(size_t)(gr + 8)*128 + (col >> 1)] = hi;
                g_hidl[(size_t)(gr + 8)*128 + (col >> 1)] = lo;
            }
        }
    } else {
        float pe[NJ], po[NJ];
        #pragma unroll
        for (int nj = 0; nj < NJ; nj++) { pe[nj] = 0.f; po[nj] = 0.f; }
        #pragma unroll
        for (int mi = 0; mi < 2; mi++) {
            const int row = wm*32 + mi*16 + g;
            const int gr  = r0 + row;
            #pragma unroll
            for (int nj = 0; nj < NJ; nj++) {
                const int col = wn*NTW + nj*8 + cq*2;
                float b0 = sBias[col], b1 = sBias[col + 1];
                float v0 = tanhf(acc[mi][nj][0] + b0);
                float v1 = tanhf(acc[mi][nj][1] + b1);
                float v2 = tanhf(acc[mi][nj][2] + b0);
                float v3 = tanhf(acc[mi][nj][3] + b1);
                *(float2*)(outF + (size_t)gr*64 + col)       = make_float2(v0, v1);
                *(float2*)(outF + (size_t)(gr + 8)*64 + col) = make_float2(v2, v3);
                if (EPI == 1) {
                    uint32_t hi, lo;
                    splitp(v0, v1, hi, lo);
                    g_x2h[(size_t)gr*64 + (col >> 1)] = hi;
                    g_x2l[(size_t)gr*64 + (col >> 1)] = lo;
                    splitp(v2, v3, hi, lo);
                    g_x2h[(size_t)(gr + 8)*64 + (col >> 1)] = hi;
                    g_x2l[(size_t)(gr + 8)*64 + (col >> 1)] = lo;
                }
                pe[nj] += v0 + v2;
                po[nj] += v1 + v3;
            }
        }
        #pragma unroll
        for (int nj = 0; nj < NJ; nj++) {
            pe[nj] += __shfl_down_sync(0xffffffffu, pe[nj], 16);
            pe[nj] += __shfl_down_sync(0xffffffffu, pe[nj], 8);
            pe[nj] += __shfl_down_sync(0xffffffffu, pe[nj], 4);
            po[nj] += __shfl_down_sync(0xffffffffu, po[nj], 16);
            po[nj] += __shfl_down_sync(0xffffffffu, po[nj], 8);
            po[nj] += __shfl_down_sync(0xffffffffu, po[nj], 4);
        }
        if (lane < 4) {
            #pragma unroll
            for (int nj = 0; nj < NJ; nj++) {
                const int col = wn*NTW + nj*8 + lane*2;
                colsum[wm*64 + col]     = pe[nj];
                colsum[wm*64 + col + 1] = po[nj];
            }
        }
        __syncthreads();
        if (tid < 64) {
            float s = 0.f;
            #pragma unroll
            for (int w = 0; w < WM; w++) s += colsum[w*64 + tid];
            float m = s * (1.f / 128.f);
            if (EPI == 1) g_hmean[blockIdx.y*64 + tid]  = m;
            else          g_msgmean[blockIdx.y*64 + tid] = m;
        }
    }
}

// =====================================================================
// K5: modulator hidden (merged) + mod_out -> W_new, decay_new
// Each block: recompute hid[64][8] for its cell c from means/stats,
// then stream its o-slice of mod_w2.
// =====================================================================
__global__ void __launch_bounds__(256)
modout_kernel(const float* __restrict__ mw1,   // modulator w1 [NC,133,64]
              const float* __restrict__ mb1,   // [NC,64]
              const float* __restrict__ mw2,   // [NC,64,16512]
              const float* __restrict__ mb2,   // [NC,16512]
              const float* __restrict__ W,
              const float* __restrict__ decay,
              const float* __restrict__ drift,
              const float* __restrict__ s1,
              const float* __restrict__ s2,
              float* __restrict__ outW,
              float* __restrict__ outD)
{
    __shared__ float sW1[PMOD_IN*64];    // 34048 B
    __shared__ float mi[8][134];
    __shared__ float hidT[512];          // [h][b]
    const int c   = blockIdx.y;
    const int tid = threadIdx.x;
    const int b   = tid >> 5;
    const int lane = tid & 31;

    // load mw1[c] (coalesced)
    for (int t = tid; t < PMOD_IN*64; t += 256)
        sW1[t] = mw1[(size_t)c*PMOD_IN*64 + t];

    // build mod_input per batch b (warp b)
    {
        const int bc = (b << 6) | c;
        for (int i = lane; i < 64; i += 32) {
            mi[b][i]      = g_hmean[bc*PDN + i];
            mi[b][64 + i] = g_msgmean[bc*PDN + i];
        }
        float ds = 0.f;
        #pragma unroll
        for (int i = 0; i < 4; i++) ds += decay[(size_t)bc*PN + lane + i*32];
        #pragma unroll
        for (int off = 16; off; off >>= 1)
            ds += __shfl_down_sync(0xffffffffu, ds, off);
        if (lane == 0) {
            mi[b][128] = g_wstats[bc];
            mi[b][129] = ds * (1.f/PN);
            mi[b][130] = drift[bc];
            mi[b][131] = s1[b];
            mi[b][132] = s2[b];
        }
    }
    __syncthreads();

    // hid GEMV: thread (b, lane) handles j = lane and lane+32
    #pragma unroll
    for (int jo = 0; jo < 2; jo++) {
        const int j = lane + jo*32;
        float acc = mb1[c*PHMOD + j];
        for (int i = 0; i < PMOD_IN; i++) acc += mi[b][i] * sW1[i*64 + j];
        hidT[j*8 + b] = tanhf(acc);
    }
    __syncthreads();

    const int o0 = (blockIdx.x * 256 + tid) * 4;
    if (o0 >= PMOD_OUT) return;

    float4 acc[8];
    const float4 bias = *(const float4*)(mb2 + (size_t)c*PMOD_OUT + o0);
    #pragma unroll
    for (int bb = 0; bb < 8; bb++) acc[bb] = bias;

    const float* wp = mw2 + (size_t)c*PHMOD*PMOD_OUT + o0;
    #pragma unroll 4
    for (int hh = 0; hh < PHMOD; hh++) {
        float4 wv = __ldcs((const float4*)(wp + (size_t)hh*PMOD_OUT));
        #pragma unroll
        for (int bb = 0; bb < 8; bb++) {
            float hv = hidT[hh*8 + bb];
            acc[bb].x += hv * wv.x;
            acc[bb].y += hv * wv.y;
            acc[bb].z += hv * wv.z;
            acc[bb].w += hv * wv.w;
        }
    }

    if (o0 < PN*PN) {
        #pragma unroll
        for (int bb = 0; bb < 8; bb++) {
            size_t idx = ((size_t)(bb*PNC + c))*(PN*PN) + o0;
            float4 wold = __ldcs((const float4*)(W + idx));
            float4 r;
            r.x = wold.x + acc[bb].x; r.y = wold.y + acc[bb].y;
            r.z = wold.z + acc[bb].z; r.w = wold.w + acc[bb].w;
            __stcs((float4*)(outW + idx), r);
        }
    } else {
        const int oo = o0 - PN*PN;
        #pragma unroll
        for (int bb = 0; bb < 8; bb++) {
            size_t idx = (size_t)(bb*PNC + c)*PN + oo;
            outD[idx+0] = decay[idx+0] + acc[bb].x;
            outD[idx+1] = decay[idx+1] + acc[bb].y;
            outD[idx+2] = decay[idx+2] + acc[bb].z;
            outD[idx+3] = decay[idx+3] + acc[bb].w;
        }
    }
}

// =====================================================================
extern "C" void kernel_launch(void* const* d_in, const int* in_sizes, int n_in,
                              void* d_out, int out_size)
{
    const float* h     = (const float*)d_in[0];
    const float* msg   = (const float*)d_in[1];
    const float* W     = (const float*)d_in[2];
    const float* decay = (const float*)d_in[3];
    const float* drift = (const float*)d_in[4];
    const float* s1    = (const float*)d_in[5];
    const float* s2    = (const float*)d_in[6];
    const float* Haug  = (const float*)d_in[7];
    const float* nid   = (const float*)d_in[8];
    const float* sw1   = (const float*)d_in[9];
    const float* sb1   = (const float*)d_in[10];
    const float* sw2   = (const float*)d_in[11];
    const float* sb2   = (const float*)d_in[12];
    const float* mw1   = (const float*)d_in[13];
    const float* mb1   = (const float*)d_in[14];
    const float* mw2   = (const float*)d_in[15];
    const float* mb2   = (const float*)d_in[16];
    const float* injW  = (const float*)d_in[17];
    const float* injB  = (const float*)d_in[18];
    const float* modw1 = (const float*)d_in[19];
    const float* modb1 = (const float*)d_in[20];
    const float* modw2 = (const float*)d_in[21];
    const float* modb2 = (const float*)d_in[22];

    float* out  = (float*)d_out;
    float* outH = out;                      // h_new
    float* outM = out + 4194304;            // msg_new
    float* outW = out + 8388608;            // W_new
    float* outD = out + 16777216;           // decay_new

    const int smem1  = (128*129 + 128*68 + 64 + 128 + 8) * 4;
    // L1 (MT=64, NT=128): 2*(16384+32768) + 1536
    const int smemL1 = 2*49152 + 1536;
    // L2 (MT=128, NT=64): 2*(32768+16384) + 1536
    const int smemL2 = 2*49152 + 1536;

    cudaFuncSetAttribute(recv_kernel,
        cudaFuncAttributeMaxDynamicSharedMemorySize, smem1);
    cudaFuncSetAttribute(gemm_kernel<64,192,128,0,0,0>,
        cudaFuncAttributeMaxDynamicSharedMemorySize, smemL1);
    cudaFuncSetAttribute(gemm_kernel<128,256,64,1,2,1>,
        cudaFuncAttributeMaxDynamicSharedMemorySize, smemL2);
    cudaFuncSetAttribute(gemm_kernel<64,128,128,0,1,2>,
        cudaFuncAttributeMaxDynamicSharedMemorySize, smemL1);
    cudaFuncSetAttribute(gemm_kernel<128,256,64,2,2,3>,
        cudaFuncAttributeMaxDynamicSharedMemorySize, smemL2);

    // K1: recv + weight splits (merged)
    recv_kernel<<<CELLS + WSPLIT_BLOCKS, 256, smem1>>>(
        W, msg, h, nid, Haug, injW, injB, sw1, sw2, mw1, mw2);

    // K2: state L1 -> hidden  (x = n-chunk for A L2-reuse)
    gemm_kernel<64,192,128,0,0,0><<<dim3(2,1024), 256, smemL1>>>(sb1, nullptr);
    // K3: state L2 -> h_new + X2[:,0:64] + h_mean
    gemm_kernel<128,256,64,1,2,1><<<dim3(1,512), 256, smemL2>>>(sb2, outH);
    // K4: msg L1 -> hidden
    gemm_kernel<64,128,128,0,1,2><<<dim3(2,1024), 256, smemL1>>>(mb1, nullptr);
    // K5: msg L2 -> msg_new + msg_mean
    gemm_kernel<128,256,64,2,2,3><<<dim3(1,512), 256, smemL2>>>(mb2, outM);

    // K6: modulator (hidden + output fused) -> W_new, decay_new
    dim3 g5((PMOD_OUT + 1023)/1024, PNC);
    modout_kernel<<<g5, 256>>>(modw1, modb1, modw2, modb2, W, decay,
                               drift, s1, s2, outW, outD);
}

// round 15
// speedup vs baseline: 1.0297x; 1.0297x over previous
#include <cuda_runtime.h>
#include <cuda_bf16.h>
#include <cstdint>
#include <math.h>

// ---------------- problem constants ----------------
#define PB   8
#define PNC  64
#define PN   128
#define PDN  64
#define PALPHA 2
#define PHMOD 64
#define PMOD_IN  133
#define PMOD_OUT 16512   // N*N + N

#define ROWS_TOTAL (PB*PNC*PN)        // 65536
#define CELLS      (PB*PNC)           // 512
#define WSPLIT_BLOCKS 384             // 98304/256

typedef unsigned long long u64;

// ---------------- scratch (device globals; no runtime alloc) ----------------
__device__ uint32_t g_x1f[ROWS_TOTAL*192];  // state-MLP input, tf32  (50 MB)
__device__ uint32_t g_x2f[ROWS_TOTAL*128];  // msg-MLP input, tf32    (33 MB)
__device__ uint32_t g_hidh[ROWS_TOTAL*128]; // hidden split bf16 hi
__device__ uint32_t g_hidl[ROWS_TOTAL*128]; // hidden split bf16 lo
__device__ uint32_t g_w1sf[256*192];        // state_w1 tf32
__device__ uint32_t g_w1mf[256*128];        // msg_w1 tf32
__device__ uint32_t g_w2sh[64*128], g_w2sl[64*128];   // state_w2 split
__device__ uint32_t g_w2mh[64*128], g_w2ml[64*128];   // msg_w2 split

__device__ float g_wstats[CELLS];
__device__ float g_hmean[CELLS*PDN];
__device__ float g_msgmean[CELLS*PDN];

// ---------------- helpers ----------------
__device__ __forceinline__ uint32_t smem_to_u32(const void* p) {
    uint32_t a;
    asm("{ .reg .u64 t; cvta.to.shared.u64 t, %1; cvt.u32.u64 %0, t; }"
        : "=r"(a) : "l"(p));
    return a;
}
__device__ __forceinline__ uint32_t tf32r(float v) {
    uint32_t r;
    asm("cvt.rna.tf32.f32 %0, %1;" : "=r"(r) : "f"(v));
    return r;
}
__device__ __forceinline__ void splitp(float v0, float v1, uint32_t& hi, uint32_t& lo) {
    __nv_bfloat16 h0 = __float2bfloat16(v0), h1 = __float2bfloat16(v1);
    float r0 = v0 - __bfloat162float(h0), r1 = v1 - __bfloat162float(h1);
    __nv_bfloat16 l0 = __float2bfloat16(r0), l1 = __float2bfloat16(r1);
    hi = (uint32_t)__bfloat16_as_ushort(h0) | ((uint32_t)__bfloat16_as_ushort(h1) << 16);
    lo = (uint32_t)__bfloat16_as_ushort(l0) | ((uint32_t)__bfloat16_as_ushort(l1) << 16);
}
// per-64-b16-col-chunk swizzled layout: row stride 128B, 16B granule xor
__device__ __forceinline__ uint32_t coff(int r, int k) {
    return (uint32_t)((r << 7) + ((((k >> 3) & 7) ^ (r & 7)) << 4) + ((k & 7) << 1));
}
__device__ __forceinline__ void ldsm4(uint32_t r[4], uint32_t a) {
    asm volatile("ldmatrix.sync.aligned.m8n8.x4.shared.b16 {%0,%1,%2,%3}, [%4];"
        : "=r"(r[0]), "=r"(r[1]), "=r"(r[2]), "=r"(r[3]) : "r"(a));
}
__device__ __forceinline__ void mma16816(float* c, const uint32_t* a, const uint32_t* b) {
    asm volatile("mma.sync.aligned.m16n8k16.row.col.f32.bf16.bf16.f32 "
        "{%0,%1,%2,%3}, {%4,%5,%6,%7}, {%8,%9}, {%0,%1,%2,%3};"
        : "+f"(c[0]), "+f"(c[1]), "+f"(c[2]), "+f"(c[3])
        : "r"(a[0]), "r"(a[1]), "r"(a[2]), "r"(a[3]), "r"(b[0]), "r"(b[1]));
}
__device__ __forceinline__ void mma1688t(float* c, const uint32_t* a, const uint32_t* b) {
    asm volatile("mma.sync.aligned.m16n8k8.row.col.f32.tf32.tf32.f32 "
        "{%0,%1,%2,%3}, {%4,%5,%6,%7}, {%8,%9}, {%0,%1,%2,%3};"
        : "+f"(c[0]), "+f"(c[1]), "+f"(c[2]), "+f"(c[3])
        : "r"(a[0]), "r"(a[1]), "r"(a[2]), "r"(a[3]), "r"(b[0]), "r"(b[1]));
}
#define CP16(dst, src) \
    asm volatile("cp.async.cg.shared.global [%0], [%1], 16;" :: "r"(dst), "l"(src))
#define CP_COMMIT() asm volatile("cp.async.commit_group;" ::: "memory")
#define CP_WAIT1()  asm volatile("cp.async.wait_group 1;" ::: "memory")

// f32x2 packed fma
__device__ __forceinline__ u64 pk2(float a, float b) {
    u64 r;
    asm("mov.b64 %0, {%1,%2};" : "=l"(r)
        : "r"(__float_as_uint(a)), "r"(__float_as_uint(b)));
    return r;
}
__device__ __forceinline__ void upk2(u64 v, float& a, float& b) {
    unsigned int x, y;
    asm("mov.b64 {%0,%1}, %2;" : "=r"(x), "=r"(y) : "l"(v));
    a = __uint_as_float(x); b = __uint_as_float(y);
}
__device__ __forceinline__ void fma2(u64& d, u64 a, u64 b) {
    asm("fma.rn.f32x2 %0, %1, %2, %0;" : "+l"(d) : "l"(a), "l"(b));
}

// =====================================================================
// K1: blocks [0,512): received = W @ msg (+ inject, + mean|W|) -> operands
//     blocks [512,896): weight prep (tf32 w1s/w1m, split w2s/w2m)
// =====================================================================
__global__ void __launch_bounds__(256)
recv_kernel(const float* __restrict__ W,
            const float* __restrict__ msg,
            const float* __restrict__ h,
            const float* __restrict__ nid,
            const float* __restrict__ Haug,
            const float* __restrict__ injW,
            const float* __restrict__ injB,
            const float* __restrict__ sw1,
            const float* __restrict__ sw2,
            const float* __restrict__ mw1,
            const float* __restrict__ mw2)
{
    const int tid = threadIdx.x;

    if (blockIdx.x >= CELLS) {
        const int p = (blockIdx.x - CELLS) * 256 + tid;
        if (p < 49152) {
            g_w1sf[p] = tf32r(sw1[p]);
        } else if (p < 81920) {
            g_w1mf[p - 49152] = tf32r(mw1[p - 49152]);
        } else if (p < 90112) {
            int lp = p - 81920;
            float2 v = ((const float2*)sw2)[lp];
            uint32_t hi, lo; splitp(v.x, v.y, hi, lo);
            g_w2sh[lp] = hi; g_w2sl[lp] = lo;
        } else if (p < 98304) {
            int lp = p - 90112;
            float2 v = ((const float2*)mw2)[lp];
            uint32_t hi, lo; splitp(v.x, v.y, hi, lo);
            g_w2mh[lp] = hi; g_w2ml[lp] = lo;
        }
        return;
    }

    extern __shared__ float sm[];
    float* Ws  = sm;                      // 128*129
    float* Ms  = Ws + 128*129;            // 128*68
    float* cs  = Ms + 128*68;             // 64
    float* inj = cs + 64;                 // 128
    float* red = inj + 128;               // 8

    const int bc  = blockIdx.x;
    const int b   = bc >> 6;
    const int c   = bc & 63;

    const size_t wbase = (size_t)bc * (PN*PN);
    const size_t mbase = (size_t)bc * (PN*PDN);

    float wsum = 0.f;
    for (int idx = tid; idx < PN*PN; idx += 256) {
        int i = idx >> 7, j = idx & 127;
        float v = W[wbase + idx];
        Ws[i*129 + j] = v;
        wsum += fabsf(v);
    }
    for (int idx = tid; idx < PN*PDN; idx += 256) {
        int j = idx >> 6, d = idx & 63;
        Ms[j*68 + d] = msg[mbase + idx];
    }
    if (tid < PDN) cs[tid] = Haug[(size_t)b*(PNC*PDN) + c*PDN + tid];

    #pragma unroll
    for (int off = 16; off; off >>= 1)
        wsum += __shfl_down_sync(0xffffffffu, wsum, off);
    if ((tid & 31) == 0) red[tid >> 5] = wsum;
    __syncthreads();
    if (tid == 0) {
        float s = 0.f;
        #pragma unroll
        for (int w = 0; w < 8; w++) s += red[w];
        g_wstats[bc] = s * (1.f / 16384.f);
    }

    if (tid < PALPHA*PDN) {
        int o = tid;
        float a = injB[c*(PALPHA*PDN) + o];
        const float* iw = injW + ((size_t)c*(PALPHA*PDN) + o)*PDN;
        #pragma unroll 8
        for (int i = 0; i < PDN; i++) a += cs[i] * iw[i];
        inj[o] = a;
    }

    // tf32 h -> X1[:,0:64], nid -> X1[:,128:192]
    for (int t = tid; t < 128*64; t += 256) {
        int r = t >> 6, d = t & 63;
        int gr = bc*128 + r;
        g_x1f[(size_t)gr*192 + d]       = tf32r(h[((size_t)bc*128 + r)*64 + d]);
        g_x1f[(size_t)gr*192 + 128 + d] = tf32r(nid[((size_t)c*128 + r)*64 + d]);
    }
    __syncthreads();

    const int rp = tid >> 2;
    const int d0 = (tid & 3) * 16;
    const int i0 = 2*rp, i1 = 2*rp + 1;

    u64 a0[8], a1[8];
    #pragma unroll
    for (int q = 0; q < 8; q++) { a0[q] = 0ull; a1[q] = 0ull; }

    const float* wr0 = Ws + i0*129;
    const float* wr1 = Ws + i1*129;
    #pragma unroll 2
    for (int j = 0; j < PN; j++) {
        float w0 = wr0[j];
        float w1v = wr1[j];
        u64 wp0 = pk2(w0, w0);
        u64 wp1 = pk2(w1v, w1v);
        const u64* mp = (const u64*)(Ms + j*68 + d0);
        #pragma unroll
        for (int q = 0; q < 8; q++) {
            u64 m = mp[q];
            fma2(a0[q], m, wp0);
            fma2(a1[q], m, wp1);
        }
    }

    const int gr0 = bc*128 + i0, gr1 = bc*128 + i1;
    #pragma unroll
    for (int q = 0; q < 8; q++) {
        float x, y; upk2(a0[q], x, y);
        if (rp == 0) { x += inj[d0 + 2*q]; y += inj[d0 + 2*q + 1]; }
        uint32_t tx = tf32r(x), ty = tf32r(y);
        g_x1f[(size_t)gr0*192 + 64 + d0 + 2*q]     = tx;
        g_x1f[(size_t)gr0*192 + 64 + d0 + 2*q + 1] = ty;
        g_x2f[(size_t)gr0*128 + 64 + d0 + 2*q]     = tx;
        g_x2f[(size_t)gr0*128 + 64 + d0 + 2*q + 1] = ty;
        upk2(a1[q], x, y);
        if (rp == 0) { x += inj[64 + d0 + 2*q]; y += inj[64 + d0 + 2*q + 1]; }
        tx = tf32r(x); ty = tf32r(y);
        g_x1f[(size_t)gr1*192 + 64 + d0 + 2*q]     = tx;
        g_x1f[(size_t)gr1*192 + 64 + d0 + 2*q + 1] = ty;
        g_x2f[(size_t)gr1*128 + 64 + d0 + 2*q]     = tx;
        g_x2f[(size_t)gr1*128 + 64 + d0 + 2*q + 1] = ty;
    }
}

// =====================================================================
// Layer-1 GEMM (TF32, single pass): C[MT x NT] = A[MT x K] @ B[NT x K]^T,
// tanh(+bias) -> split bf16 hidden. KC=32 fp32 chunks, 2-stage cp.async.
// 256 threads, 8 warps (MT/32 M x rest N). Grid: x = n-chunk, y = rows.
// =====================================================================
template<int MT, int K, int NT, int ASRC, int BSRC>
__global__ void __launch_bounds__(256)
gemm_tf32_kernel(const float* __restrict__ bias)
{
    constexpr int NC    = K / 32;       // fp32 k-chunks
    constexpr int ABYT  = MT * 128;     // A bytes per stage
    constexpr int STAGE = ABYT + NT * 128;
    constexpr int WM    = MT / 32;
    constexpr int WN    = 8 / WM;
    constexpr int NTW   = NT / WN;
    constexpr int NJ    = NTW / 8;
    constexpr int NPF   = NTW / 16;

    extern __shared__ unsigned char smx[];
    float* sBias = (float*)(smx + 2*STAGE);

    const uint32_t* Af = (ASRC == 0) ? g_x1f  : g_x2f;
    const uint32_t* Bf = (BSRC == 0) ? g_w1sf : g_w1mf;

    const int tid  = threadIdx.x;
    const int lane = tid & 31;
    const int wid  = tid >> 5;
    const int wm   = wid % WM;
    const int wn   = wid / WM;
    const int r0   = blockIdx.y * MT;
    const int n0   = blockIdx.x * NT;
    const uint32_t sb = smem_to_u32(smx);

    auto load_stage = [&](int s, int chunk) {
        const uint32_t base = sb + s*STAGE;
        const int kc = chunk * 32;                  // fp32 offset into row
        for (int t = tid; t < MT*8; t += 256) {
            int r = t >> 3, g = t & 7;
            uint32_t d = base + (r << 7) + ((uint32_t)(g ^ (r & 7)) << 4);
            CP16(d, Af + (size_t)(r0 + r)*K + kc + g*4);
        }
        for (int t = tid; t < NT*8; t += 256) {
            int r = t >> 3, g = t & 7;
            uint32_t d = base + ABYT + (r << 7) + ((uint32_t)(g ^ (r & 7)) << 4);
            CP16(d, Bf + (size_t)(n0 + r)*K + kc + g*4);
        }
    };

    load_stage(0, 0);
    CP_COMMIT();
    for (int t = tid; t < NT; t += 256) sBias[t] = bias[n0 + t];

    const int a_r = wm*32 + ((lane >> 3) & 1)*8 + (lane & 7);
    const int a_k = (lane >> 4) * 8;
    const int b_n = wn*NTW + (lane >> 4)*8 + (lane & 7);
    const int b_k = ((lane >> 3) & 1) * 8;

    float acc[2][NJ][4];
    #pragma unroll
    for (int mi = 0; mi < 2; mi++)
        #pragma unroll
        for (int nj = 0; nj < NJ; nj++)
            #pragma unroll
            for (int q = 0; q < 4; q++) acc[mi][nj][q] = 0.f;

    #pragma unroll 1
    for (int c = 0; c < NC; c++) {
        if (c + 1 < NC) load_stage((c + 1) & 1, c + 1);
        CP_COMMIT();
        CP_WAIT1();
        __syncthreads();

        const uint32_t st = sb + (c & 1)*STAGE;
        #pragma unroll
        for (int ks = 0; ks < 4; ks++) {
            const int k0 = ks * 16;                 // b16 cols (= 8 fp32)
            uint32_t af[2][4], bf[NPF][4];
            #pragma unroll
            for (int mi = 0; mi < 2; mi++)
                ldsm4(af[mi], st + coff(a_r + mi*16, k0 + a_k));
            #pragma unroll
            for (int np = 0; np < NPF; np++)
                ldsm4(bf[np], st + ABYT + coff(b_n + np*16, k0 + b_k));
            #pragma unroll
            for (int mi = 0; mi < 2; mi++)
                #pragma unroll
                for (int nj = 0; nj < NJ; nj++)
                    mma1688t(acc[mi][nj], af[mi], &bf[nj >> 1][(nj & 1)*2]);
        }
        __syncthreads();
    }

    // ---- epilogue: tanh(+bias) -> split bf16 hidden ----
    const int g  = lane >> 2;
    const int cq = lane & 3;
    #pragma unroll
    for (int mi = 0; mi < 2; mi++) {
        const int row = wm*32 + mi*16 + g;
        const int gr  = r0 + row;
        #pragma unroll
        for (int nj = 0; nj < NJ; nj++) {
            const int colL = wn*NTW + nj*8 + cq*2;
            const int col  = n0 + colL;
            float b0 = sBias[colL], b1 = sBias[colL + 1];
            float v0 = tanhf(acc[mi][nj][0] + b0);
            float v1 = tanhf(acc[mi][nj][1] + b1);
            float v2 = tanhf(acc[mi][nj][2] + b0);
            float v3 = tanhf(acc[mi][nj][3] + b1);
            uint32_t hi, lo;
            splitp(v0, v1, hi, lo);
            g_hidh[(size_t)gr*128 + (col >> 1)] = hi;
            g_hidl[(size_t)gr*128 + (col >> 1)] = lo;
            splitp(v2, v3, hi, lo);
            g_hidh[(size_t)(gr + 8)*128 + (col >> 1)] = hi;
            g_hidl[(size_t)(gr + 8)*128 + (col >> 1)] = lo;
        }
    }
}

// =====================================================================
// Layer-2 GEMM (split bf16, 3-pass exact): C[128 x 64] = hid @ w2^T,
// fp32 out + means (+ X2 tf32 feed for EPI==1). KC=64 chunks, 2-stage.
// =====================================================================
template<int EPI, int BSRC>
__global__ void __launch_bounds__(256)
gemm_l2_kernel(const float* __restrict__ bias, float* __restrict__ outF)
{
    constexpr int MT = 128, K = 256, NT = 64;
    constexpr int KP    = K / 2;
    constexpr int NC    = K / 64;
    constexpr int ABYT  = MT * 256;
    constexpr int STAGE = ABYT + NT * 256;
    constexpr int WM    = 4, WN = 2, NTW = 32, NJ = 4, NPF = 2;

    extern __shared__ unsigned char smx[];
    float* sBias  = (float*)(smx + 2*STAGE);
    float* colsum = sBias + NT;

    const uint32_t* Ahi = g_hidh;
    const uint32_t* Alo = g_hidl;
    const uint32_t* Bhi = (BSRC == 0) ? g_w2sh : g_w2mh;
    const uint32_t* Blo = (BSRC == 0) ? g_w2sl : g_w2ml;

    const int tid  = threadIdx.x;
    const int lane = tid & 31;
    const int wid  = tid >> 5;
    const int wm   = wid % WM;
    const int wn   = wid / WM;
    const int r0   = blockIdx.y * MT;
    const int n0   = 0;
    const uint32_t sb = smem_to_u32(smx);

    auto load_stage = [&](int s, int chunk) {
        const uint32_t base = sb + s*STAGE;
        const int kc = chunk * 32;
        for (int t = tid; t < MT*8; t += 256) {
            int r = t >> 3, g = t & 7;
            uint32_t d = base + (r << 7) + ((uint32_t)(g ^ (r & 7)) << 4);
            const size_t go = (size_t)(r0 + r)*KP + kc + g*4;
            CP16(d,          Ahi + go);
            CP16(d + MT*128, Alo + go);
        }
        for (int t = tid; t < NT*8; t += 256) {
            int r = t >> 3, g = t & 7;
            uint32_t d = base + ABYT + (r << 7) + ((uint32_t)(g ^ (r & 7)) << 4);
            const size_t go = (size_t)(n0 + r)*KP + kc + g*4;
            CP16(d,          Bhi + go);
            CP16(d + NT*128, Blo + go);
        }
    };

    load_stage(0, 0);
    CP_COMMIT();
    for (int t = tid; t < NT; t += 256) sBias[t] = bias[t];

    const int a_r = wm*32 + ((lane >> 3) & 1)*8 + (lane & 7);
    const int a_k = (lane >> 4) * 8;
    const int b_n = wn*NTW + (lane >> 4)*8 + (lane & 7);
    const int b_k = ((lane >> 3) & 1) * 8;

    float acc[2][NJ][4];
    #pragma unroll
    for (int mi = 0; mi < 2; mi++)
        #pragma unroll
        for (int nj = 0; nj < NJ; nj++)
            #pragma unroll
            for (int q = 0; q < 4; q++) acc[mi][nj][q] = 0.f;

    #pragma unroll 1
    for (int c = 0; c < NC; c++) {
        if (c + 1 < NC) load_stage((c + 1) & 1, c + 1);
        CP_COMMIT();
        CP_WAIT1();
        __syncthreads();

        const uint32_t st = sb + (c & 1)*STAGE;
        #pragma unroll
        for (int ks = 0; ks < 4; ks++) {
            const int k0 = ks * 16;
            uint32_t ah[2][4], al[2][4], bh[NPF][4], bl[NPF][4];
            #pragma unroll
            for (int mi = 0; mi < 2; mi++) {
                uint32_t o = coff(a_r + mi*16, k0 + a_k);
                ldsm4(ah[mi], st + o);
                ldsm4(al[mi], st + MT*128 + o);
            }
            #pragma unroll
            for (int np = 0; np < NPF; np++) {
                uint32_t o = coff(b_n + np*16, k0 + b_k);
                ldsm4(bh[np], st + ABYT + o);
                ldsm4(bl[np], st + ABYT + NT*128 + o);
            }
            #pragma unroll
            for (int mi = 0; mi < 2; mi++)
                #pragma unroll
                for (int nj = 0; nj < NJ; nj++) {
                    const uint32_t* bph = &bh[nj >> 1][(nj & 1)*2];
                    const uint32_t* bpl = &bl[nj >> 1][(nj & 1)*2];
                    mma16816(acc[mi][nj], ah[mi], bph);
                    mma16816(acc[mi][nj], ah[mi], bpl);
                    mma16816(acc[mi][nj], al[mi], bph);
                }
        }
        __syncthreads();
    }

    // ---- epilogue: fp32 out, means, optional X2 tf32 feed ----
    const int g  = lane >> 2;
    const int cq = lane & 3;
    float pe[NJ], po[NJ];
    #pragma unroll
    for (int nj = 0; nj < NJ; nj++) { pe[nj] = 0.f; po[nj] = 0.f; }
    #pragma unroll
    for (int mi = 0; mi < 2; mi++) {
        const int row = wm*32 + mi*16 + g;
        const int gr  = r0 + row;
        #pragma unroll
        for (int nj = 0; nj < NJ; nj++) {
            const int col = wn*NTW + nj*8 + cq*2;
            float b0 = sBias[col], b1 = sBias[col + 1];
            float v0 = tanhf(acc[mi][nj][0] + b0);
            float v1 = tanhf(acc[mi][nj][1] + b1);
            float v2 = tanhf(acc[mi][nj][2] + b0);
            float v3 = tanhf(acc[mi][nj][3] + b1);
            *(float2*)(outF + (size_t)gr*64 + col)       = make_float2(v0, v1);
            *(float2*)(outF + (size_t)(gr + 8)*64 + col) = make_float2(v2, v3);
            if (EPI == 1) {
                g_x2f[(size_t)gr*128 + col]           = tf32r(v0);
                g_x2f[(size_t)gr*128 + col + 1]       = tf32r(v1);
                g_x2f[(size_t)(gr + 8)*128 + col]     = tf32r(v2);
                g_x2f[(size_t)(gr + 8)*128 + col + 1] = tf32r(v3);
            }
            pe[nj] += v0 + v2;
            po[nj] += v1 + v3;
        }
    }
    #pragma unroll
    for (int nj = 0; nj < NJ; nj++) {
        pe[nj] += __shfl_down_sync(0xffffffffu, pe[nj], 16);
        pe[nj] += __shfl_down_sync(0xffffffffu, pe[nj], 8);
        pe[nj] += __shfl_down_sync(0xffffffffu, pe[nj], 4);
        po[nj] += __shfl_down_sync(0xffffffffu, po[nj], 16);
        po[nj] += __shfl_down_sync(0xffffffffu, po[nj], 8);
        po[nj] += __shfl_down_sync(0xffffffffu, po[nj], 4);
    }
    if (lane < 4) {
        #pragma unroll
        for (int nj = 0; nj < NJ; nj++) {
            const int col = wn*NTW + nj*8 + lane*2;
            colsum[wm*64 + col]     = pe[nj];
            colsum[wm*64 + col + 1] = po[nj];
        }
    }
    __syncthreads();
    if (tid < 64) {
        float s = 0.f;
        #pragma unroll
        for (int w = 0; w < WM; w++) s += colsum[w*64 + tid];
        float m = s * (1.f / 128.f);
        if (EPI == 1) g_hmean[blockIdx.y*64 + tid]   = m;
        else          g_msgmean[blockIdx.y*64 + tid] = m;
    }
}

// =====================================================================
// K6: modulator hidden (fused) + mod_out -> W_new, decay_new
// =====================================================================
__global__ void __launch_bounds__(256)
modout_kernel(const float* __restrict__ mw1,
              const float* __restrict__ mb1,
              const float* __restrict__ mw2,
              const float* __restrict__ mb2,
              const float* __restrict__ W,
              const float* __restrict__ decay,
              const float* __restrict__ drift,
              const float* __restrict__ s1,
              const float* __restrict__ s2,
              float* __restrict__ outW,
              float* __restrict__ outD)
{
    __shared__ float sW1[PMOD_IN*64];
    __shared__ float mi[8][134];
    __shared__ float hidT[512];
    const int c   = blockIdx.y;
    const int tid = threadIdx.x;
    const int b   = tid >> 5;
    const int lane = tid & 31;

    for (int t = tid; t < PMOD_IN*64; t += 256)
        sW1[t] = mw1[(size_t)c*PMOD_IN*64 + t];

    {
        const int bc = (b << 6) | c;
        for (int i = lane; i < 64; i += 32) {
            mi[b][i]      = g_hmean[bc*PDN + i];
            mi[b][64 + i] = g_msgmean[bc*PDN + i];
        }
        float ds = 0.f;
        #pragma unroll
        for (int i = 0; i < 4; i++) ds += decay[(size_t)bc*PN + lane + i*32];
        #pragma unroll
        for (int off = 16; off; off >>= 1)
            ds += __shfl_down_sync(0xffffffffu, ds, off);
        if (lane == 0) {
            mi[b][128] = g_wstats[bc];
            mi[b][129] = ds * (1.f/PN);
            mi[b][130] = drift[bc];
            mi[b][131] = s1[b];
            mi[b][132] = s2[b];
        }
    }
    __syncthreads();

    #pragma unroll
    for (int jo = 0; jo < 2; jo++) {
        const int j = lane + jo*32;
        float acc = mb1[c*PHMOD + j];
        for (int i = 0; i < PMOD_IN; i++) acc += mi[b][i] * sW1[i*64 + j];
        hidT[j*8 + b] = tanhf(acc);
    }
    __syncthreads();

    const int o0 = (blockIdx.x * 256 + tid) * 4;
    if (o0 >= PMOD_OUT) return;

    float4 acc[8];
    const float4 bias = *(const float4*)(mb2 + (size_t)c*PMOD_OUT + o0);
    #pragma unroll
    for (int bb = 0; bb < 8; bb++) acc[bb] = bias;

    const float* wp = mw2 + (size_t)c*PHMOD*PMOD_OUT + o0;
    #pragma unroll 4
    for (int hh = 0; hh < PHMOD; hh++) {
        float4 wv = __ldcs((const float4*)(wp + (size_t)hh*PMOD_OUT));
        #pragma unroll
        for (int bb = 0; bb < 8; bb++) {
            float hv = hidT[hh*8 + bb];
            acc[bb].x += hv * wv.x;
            acc[bb].y += hv * wv.y;
            acc[bb].z += hv * wv.z;
            acc[bb].w += hv * wv.w;
        }
    }

    if (o0 < PN*PN) {
        #pragma unroll
        for (int bb = 0; bb < 8; bb++) {
            size_t idx = ((size_t)(bb*PNC + c))*(PN*PN) + o0;
            float4 wold = __ldcs((const float4*)(W + idx));
            float4 r;
            r.x = wold.x + acc[bb].x; r.y = wold.y + acc[bb].y;
            r.z = wold.z + acc[bb].z; r.w = wold.w + acc[bb].w;
            __stcs((float4*)(outW + idx), r);
        }
    } else {
        const int oo = o0 - PN*PN;
        #pragma unroll
        for (int bb = 0; bb < 8; bb++) {
            size_t idx = (size_t)(bb*PNC + c)*PN + oo;
            outD[idx+0] = decay[idx+0] + acc[bb].x;
            outD[idx+1] = decay[idx+1] + acc[bb].y;
            outD[idx+2] = decay[idx+2] + acc[bb].z;
            outD[idx+3] = decay[idx+3] + acc[bb].w;
        }
    }
}

// =====================================================================
extern "C" void kernel_launch(void* const* d_in, const int* in_sizes, int n_in,
                              void* d_out, int out_size)
{
    const float* h     = (const float*)d_in[0];
    const float* msg   = (const float*)d_in[1];
    const float* W     = (const float*)d_in[2];
    const float* decay = (const float*)d_in[3];
    const float* drift = (const float*)d_in[4];
    const float* s1    = (const float*)d_in[5];
    const float* s2    = (const float*)d_in[6];
    const float* Haug  = (const float*)d_in[7];
    const float* nid   = (const float*)d_in[8];
    const float* sw1   = (const float*)d_in[9];
    const float* sb1   = (const float*)d_in[10];
    const float* sw2   = (const float*)d_in[11];
    const float* sb2   = (const float*)d_in[12];
    const float* mw1   = (const float*)d_in[13];
    const float* mb1   = (const float*)d_in[14];
    const float* mw2   = (const float*)d_in[15];
    const float* mb2   = (const float*)d_in[16];
    const float* injW  = (const float*)d_in[17];
    const float* injB  = (const float*)d_in[18];
    const float* modw1 = (const float*)d_in[19];
    const float* modb1 = (const float*)d_in[20];
    const float* modw2 = (const float*)d_in[21];
    const float* modb2 = (const float*)d_in[22];

    float* out  = (float*)d_out;
    float* outH = out;                      // h_new
    float* outM = out + 4194304;            // msg_new
    float* outW = out + 8388608;            // W_new
    float* outD = out + 16777216;           // decay_new

    const int smem1  = (128*129 + 128*68 + 64 + 128 + 8) * 4;
    // L1 tf32 (MT=64, NT=128): 2*(8192+16384) + 512 + pad
    const int smemT1 = 2*24576 + 1024;
    // L2 (MT=128, NT=64, 3-pass): 2*(32768+16384) + 1536
    const int smemL2 = 2*49152 + 1536;

    cudaFuncSetAttribute(recv_kernel,
        cudaFuncAttributeMaxDynamicSharedMemorySize, smem1);
    cudaFuncSetAttribute(gemm_tf32_kernel<64,192,128,0,0>,
        cudaFuncAttributeMaxDynamicSharedMemorySize, smemT1);
    cudaFuncSetAttribute(gemm_tf32_kernel<64,128,128,1,1>,
        cudaFuncAttributeMaxDynamicSharedMemorySize, smemT1);
    cudaFuncSetAttribute(gemm_l2_kernel<1,0>,
        cudaFuncAttributeMaxDynamicSharedMemorySize, smemL2);
    cudaFuncSetAttribute(gemm_l2_kernel<2,1>,
        cudaFuncAttributeMaxDynamicSharedMemorySize, smemL2);

    // K1: recv + weight prep (merged)
    recv_kernel<<<CELLS + WSPLIT_BLOCKS, 256, smem1>>>(
        W, msg, h, nid, Haug, injW, injB, sw1, sw2, mw1, mw2);

    // K2: state L1 (tf32) -> hidden
    gemm_tf32_kernel<64,192,128,0,0><<<dim3(2,1024), 256, smemT1>>>(sb1);
    // K3: state L2 (exact) -> h_new + X2[:,0:64] + h_mean
    gemm_l2_kernel<1,0><<<dim3(1,512), 256, smemL2>>>(sb2, outH);
    // K4: msg L1 (tf32) -> hidden
    gemm_tf32_kernel<64,128,128,1,1><<<dim3(2,1024), 256, smemT1>>>(mb1);
    // K5: msg L2 (exact) -> msg_new + msg_mean
    gemm_l2_kernel<2,1><<<dim3(1,512), 256, smemL2>>>(mb2, outM);

    // K6: modulator (hidden + output fused) -> W_new, decay_new
    dim3 g5((PMOD_OUT + 1023)/1024, PNC);
    modout_kernel<<<g5, 256>>>(modw1, modb1, modw2, modb2, W, decay,
                               drift, s1, s2, outW, outD);
}

// round 16
// speedup vs baseline: 1.0545x; 1.0241x over previous
#include <cuda_runtime.h>
#include <cuda_bf16.h>
#include <cstdint>
#include <math.h>

// ---------------- problem constants ----------------
#define PB   8
#define PNC  64
#define PN   128
#define PDN  64
#define PALPHA 2
#define PHMOD 64
#define PMOD_IN  133
#define PMOD_OUT 16512   // N*N + N

#define ROWS_TOTAL (PB*PNC*PN)        // 65536
#define CELLS      (PB*PNC)           // 512
#define WSPLIT_BLOCKS 384             // 98304/256

typedef unsigned long long u64;

// ---------------- scratch (device globals; no runtime alloc) ----------------
__device__ uint32_t g_x1f[ROWS_TOTAL*192];  // state-MLP input, tf32  (50 MB)
__device__ uint32_t g_x2f[ROWS_TOTAL*128];  // msg-MLP input, tf32    (33 MB)
__device__ uint32_t g_hidh[ROWS_TOTAL*128]; // hidden split bf16 hi
__device__ uint32_t g_hidl[ROWS_TOTAL*128]; // hidden split bf16 lo
__device__ uint32_t g_w1sf[256*192];        // state_w1 tf32
__device__ uint32_t g_w1mf[256*128];        // msg_w1 tf32
__device__ uint32_t g_w2sh[64*128], g_w2sl[64*128];   // state_w2 split
__device__ uint32_t g_w2mh[64*128], g_w2ml[64*128];   // msg_w2 split

__device__ float g_wstats[CELLS];
__device__ float g_hmean[CELLS*PDN];
__device__ float g_msgmean[CELLS*PDN];

// ---------------- helpers ----------------
__device__ __forceinline__ uint32_t smem_to_u32(const void* p) {
    uint32_t a;
    asm("{ .reg .u64 t; cvta.to.shared.u64 t, %1; cvt.u32.u64 %0, t; }"
        : "=r"(a) : "l"(p));
    return a;
}
__device__ __forceinline__ uint32_t tf32r(float v) {
    uint32_t r;
    asm("cvt.rna.tf32.f32 %0, %1;" : "=r"(r) : "f"(v));
    return r;
}
__device__ __forceinline__ void splitp(float v0, float v1, uint32_t& hi, uint32_t& lo) {
    __nv_bfloat16 h0 = __float2bfloat16(v0), h1 = __float2bfloat16(v1);
    float r0 = v0 - __bfloat162float(h0), r1 = v1 - __bfloat162float(h1);
    __nv_bfloat16 l0 = __float2bfloat16(r0), l1 = __float2bfloat16(r1);
    hi = (uint32_t)__bfloat16_as_ushort(h0) | ((uint32_t)__bfloat16_as_ushort(h1) << 16);
    lo = (uint32_t)__bfloat16_as_ushort(l0) | ((uint32_t)__bfloat16_as_ushort(l1) << 16);
}
// per-64-b16-col-chunk swizzled layout: row stride 128B, 16B granule xor
__device__ __forceinline__ uint32_t coff(int r, int k) {
    return (uint32_t)((r << 7) + ((((k >> 3) & 7) ^ (r & 7)) << 4) + ((k & 7) << 1));
}
__device__ __forceinline__ void ldsm4(uint32_t r[4], uint32_t a) {
    asm volatile("ldmatrix.sync.aligned.m8n8.x4.shared.b16 {%0,%1,%2,%3}, [%4];"
        : "=r"(r[0]), "=r"(r[1]), "=r"(r[2]), "=r"(r[3]) : "r"(a));
}
__device__ __forceinline__ void mma16816(float* c, const uint32_t* a, const uint32_t* b) {
    asm volatile("mma.sync.aligned.m16n8k16.row.col.f32.bf16.bf16.f32 "
        "{%0,%1,%2,%3}, {%4,%5,%6,%7}, {%8,%9}, {%0,%1,%2,%3};"
        : "+f"(c[0]), "+f"(c[1]), "+f"(c[2]), "+f"(c[3])
        : "r"(a[0]), "r"(a[1]), "r"(a[2]), "r"(a[3]), "r"(b[0]), "r"(b[1]));
}
__device__ __forceinline__ void mma1688t(float* c, const uint32_t* a, const uint32_t* b) {
    asm volatile("mma.sync.aligned.m16n8k8.row.col.f32.tf32.tf32.f32 "
        "{%0,%1,%2,%3}, {%4,%5,%6,%7}, {%8,%9}, {%0,%1,%2,%3};"
        : "+f"(c[0]), "+f"(c[1]), "+f"(c[2]), "+f"(c[3])
        : "r"(a[0]), "r"(a[1]), "r"(a[2]), "r"(a[3]), "r"(b[0]), "r"(b[1]));
}
#define CP16(dst, src) \
    asm volatile("cp.async.cg.shared.global [%0], [%1], 16;" :: "r"(dst), "l"(src))
#define CP_COMMIT() asm volatile("cp.async.commit_group;" ::: "memory")
#define CP_WAIT1()  asm volatile("cp.async.wait_group 1;" ::: "memory")

// f32x2 packed fma
__device__ __forceinline__ u64 pk2(float a, float b) {
    u64 r;
    asm("mov.b64 %0, {%1,%2};" : "=l"(r)
        : "r"(__float_as_uint(a)), "r"(__float_as_uint(b)));
    return r;
}
__device__ __forceinline__ void upk2(u64 v, float& a, float& b) {
    unsigned int x, y;
    asm("mov.b64 {%0,%1}, %2;" : "=r"(x), "=r"(y) : "l"(v));
    a = __uint_as_float(x); b = __uint_as_float(y);
}
__device__ __forceinline__ void fma2(u64& d, u64 a, u64 b) {
    asm("fma.rn.f32x2 %0, %1, %2, %0;" : "+l"(d) : "l"(a), "l"(b));
}

// =====================================================================
// K1: blocks [0,512): received = W @ msg (+ inject, + mean|W|) -> operands
//     blocks [512,896): weight prep (tf32 w1s/w1m, split w2s/w2m)
// =====================================================================
__global__ void __launch_bounds__(256)
recv_kernel(const float* __restrict__ W,
            const float* __restrict__ msg,
            const float* __restrict__ h,
            const float* __restrict__ nid,
            const float* __restrict__ Haug,
            const float* __restrict__ injW,
            const float* __restrict__ injB,
            const float* __restrict__ sw1,
            const float* __restrict__ sw2,
            const float* __restrict__ mw1,
            const float* __restrict__ mw2)
{
    const int tid = threadIdx.x;

    if (blockIdx.x >= CELLS) {
        const int p = (blockIdx.x - CELLS) * 256 + tid;
        if (p < 49152) {
            g_w1sf[p] = tf32r(sw1[p]);
        } else if (p < 81920) {
            g_w1mf[p - 49152] = tf32r(mw1[p - 49152]);
        } else if (p < 90112) {
            int lp = p - 81920;
            float2 v = ((const float2*)sw2)[lp];
            uint32_t hi, lo; splitp(v.x, v.y, hi, lo);
            g_w2sh[lp] = hi; g_w2sl[lp] = lo;
        } else if (p < 98304) {
            int lp = p - 90112;
            float2 v = ((const float2*)mw2)[lp];
            uint32_t hi, lo; splitp(v.x, v.y, hi, lo);
            g_w2mh[lp] = hi; g_w2ml[lp] = lo;
        }
        return;
    }

    extern __shared__ float sm[];
    float* Ws  = sm;                      // 128*129
    float* Ms  = Ws + 128*129;            // 128*68
    float* cs  = Ms + 128*68;             // 64
    float* inj = cs + 64;                 // 128
    float* red = inj + 128;               // 8

    const int bc  = blockIdx.x;
    const int b   = bc >> 6;
    const int c   = bc & 63;

    const size_t wbase = (size_t)bc * (PN*PN);
    const size_t mbase = (size_t)bc * (PN*PDN);

    float wsum = 0.f;
    for (int idx = tid; idx < PN*PN; idx += 256) {
        int i = idx >> 7, j = idx & 127;
        float v = W[wbase + idx];
        Ws[i*129 + j] = v;
        wsum += fabsf(v);
    }
    for (int idx = tid; idx < PN*PDN; idx += 256) {
        int j = idx >> 6, d = idx & 63;
        Ms[j*68 + d] = msg[mbase + idx];
    }
    if (tid < PDN) cs[tid] = Haug[(size_t)b*(PNC*PDN) + c*PDN + tid];

    #pragma unroll
    for (int off = 16; off; off >>= 1)
        wsum += __shfl_down_sync(0xffffffffu, wsum, off);
    if ((tid & 31) == 0) red[tid >> 5] = wsum;
    __syncthreads();
    if (tid == 0) {
        float s = 0.f;
        #pragma unroll
        for (int w = 0; w < 8; w++) s += red[w];
        g_wstats[bc] = s * (1.f / 16384.f);
    }

    if (tid < PALPHA*PDN) {
        int o = tid;
        float a = injB[c*(PALPHA*PDN) + o];
        const float* iw = injW + ((size_t)c*(PALPHA*PDN) + o)*PDN;
        #pragma unroll 8
        for (int i = 0; i < PDN; i++) a += cs[i] * iw[i];
        inj[o] = a;
    }

    // tf32 h -> X1[:,0:64], nid -> X1[:,128:192]
    for (int t = tid; t < 128*64; t += 256) {
        int r = t >> 6, d = t & 63;
        int gr = bc*128 + r;
        g_x1f[(size_t)gr*192 + d]       = tf32r(h[((size_t)bc*128 + r)*64 + d]);
        g_x1f[(size_t)gr*192 + 128 + d] = tf32r(nid[((size_t)c*128 + r)*64 + d]);
    }
    __syncthreads();

    const int rp = tid >> 2;
    const int d0 = (tid & 3) * 16;
    const int i0 = 2*rp, i1 = 2*rp + 1;

    u64 a0[8], a1[8];
    #pragma unroll
    for (int q = 0; q < 8; q++) { a0[q] = 0ull; a1[q] = 0ull; }

    const float* wr0 = Ws + i0*129;
    const float* wr1 = Ws + i1*129;
    #pragma unroll 2
    for (int j = 0; j < PN; j++) {
        float w0 = wr0[j];
        float w1v = wr1[j];
        u64 wp0 = pk2(w0, w0);
        u64 wp1 = pk2(w1v, w1v);
        const u64* mp = (const u64*)(Ms + j*68 + d0);
        #pragma unroll
        for (int q = 0; q < 8; q++) {
            u64 m = mp[q];
            fma2(a0[q], m, wp0);
            fma2(a1[q], m, wp1);
        }
    }

    const int gr0 = bc*128 + i0, gr1 = bc*128 + i1;
    #pragma unroll
    for (int q = 0; q < 8; q++) {
        float x, y; upk2(a0[q], x, y);
        if (rp == 0) { x += inj[d0 + 2*q]; y += inj[d0 + 2*q + 1]; }
        uint32_t tx = tf32r(x), ty = tf32r(y);
        g_x1f[(size_t)gr0*192 + 64 + d0 + 2*q]     = tx;
        g_x1f[(size_t)gr0*192 + 64 + d0 + 2*q + 1] = ty;
        g_x2f[(size_t)gr0*128 + 64 + d0 + 2*q]     = tx;
        g_x2f[(size_t)gr0*128 + 64 + d0 + 2*q + 1] = ty;
        upk2(a1[q], x, y);
        if (rp == 0) { x += inj[64 + d0 + 2*q]; y += inj[64 + d0 + 2*q + 1]; }
        tx = tf32r(x); ty = tf32r(y);
        g_x1f[(size_t)gr1*192 + 64 + d0 + 2*q]     = tx;
        g_x1f[(size_t)gr1*192 + 64 + d0 + 2*q + 1] = ty;
        g_x2f[(size_t)gr1*128 + 64 + d0 + 2*q]     = tx;
        g_x2f[(size_t)gr1*128 + 64 + d0 + 2*q + 1] = ty;
    }
}

// =====================================================================
// Layer-1 GEMM (TF32, single pass): C[MT x NT] = A[MT x K] @ B[NT x K]^T,
// tanh(+bias) -> split bf16 hidden. KC=32 fp32 chunks, 2-stage cp.async.
// Hoisted loader addressing; 4 CTAs/SM. Grid: x = n-chunk, y = rows.
// =====================================================================
template<int MT, int K, int NT, int ASRC, int BSRC>
__global__ void __launch_bounds__(256, 4)
gemm_tf32_kernel(const float* __restrict__ bias)
{
    constexpr int NC    = K / 32;       // fp32 k-chunks
    constexpr int ABYT  = MT * 128;     // A bytes per stage
    constexpr int STAGE = ABYT + NT * 128;
    constexpr int WM    = MT / 32;
    constexpr int WN    = 8 / WM;
    constexpr int NTW   = NT / WN;
    constexpr int NJ    = NTW / 8;
    constexpr int NPF   = NTW / 16;
    constexpr int AIT   = MT / 32;      // loader iters (granules/thread)
    constexpr int BIT   = NT / 32;

    extern __shared__ unsigned char smx[];
    float* sBias = (float*)(smx + 2*STAGE);

    const uint32_t* Af = (ASRC == 0) ? g_x1f  : g_x2f;
    const uint32_t* Bf = (BSRC == 0) ? g_w1sf : g_w1mf;

    const int tid  = threadIdx.x;
    const int lane = tid & 31;
    const int wid  = tid >> 5;
    const int wm   = wid % WM;
    const int wn   = wid / WM;
    const int r0   = blockIdx.y * MT;
    const int n0   = blockIdx.x * NT;
    const uint32_t sb = smem_to_u32(smx);

    // ---- hoisted loader state: g fixed = tid&7, row base = tid>>3, +32/iter ----
    const int lr  = tid >> 3;
    const int lg  = tid & 7;
    const uint32_t dA0 = (uint32_t)((lr << 7) + ((lg ^ (lr & 7)) << 4));
    const uint32_t dB0 = dA0 + ABYT;
    const uint32_t* gA = Af + (size_t)(r0 + lr)*K + lg*4;
    const uint32_t* gB = Bf + (size_t)(n0 + lr)*K + lg*4;

    auto load_stage = [&](int s, int chunk) {
        const uint32_t base = sb + s*STAGE;
        const uint32_t* a = gA + chunk*32;
        #pragma unroll
        for (int i = 0; i < AIT; i++)
            CP16(base + dA0 + i*4096, a + (size_t)i*32*K);
        const uint32_t* b = gB + chunk*32;
        #pragma unroll
        for (int i = 0; i < BIT; i++)
            CP16(base + dB0 + i*4096, b + (size_t)i*32*K);
    };

    load_stage(0, 0);
    CP_COMMIT();
    for (int t = tid; t < NT; t += 256) sBias[t] = bias[n0 + t];

    const int a_r = wm*32 + ((lane >> 3) & 1)*8 + (lane & 7);
    const int a_k = (lane >> 4) * 8;
    const int b_n = wn*NTW + (lane >> 4)*8 + (lane & 7);
    const int b_k = ((lane >> 3) & 1) * 8;

    float acc[2][NJ][4];
    #pragma unroll
    for (int mi = 0; mi < 2; mi++)
        #pragma unroll
        for (int nj = 0; nj < NJ; nj++)
            #pragma unroll
            for (int q = 0; q < 4; q++) acc[mi][nj][q] = 0.f;

    #pragma unroll 1
    for (int c = 0; c < NC; c++) {
        if (c + 1 < NC) load_stage((c + 1) & 1, c + 1);
        CP_COMMIT();
        CP_WAIT1();
        __syncthreads();

        const uint32_t st = sb + (c & 1)*STAGE;
        #pragma unroll
        for (int ks = 0; ks < 4; ks++) {
            const int k0 = ks * 16;                 // b16 cols (= 8 fp32)
            uint32_t af[2][4], bf[NPF][4];
            #pragma unroll
            for (int mi = 0; mi < 2; mi++)
                ldsm4(af[mi], st + coff(a_r + mi*16, k0 + a_k));
            #pragma unroll
            for (int np = 0; np < NPF; np++)
                ldsm4(bf[np], st + ABYT + coff(b_n + np*16, k0 + b_k));
            #pragma unroll
            for (int mi = 0; mi < 2; mi++)
                #pragma unroll
                for (int nj = 0; nj < NJ; nj++)
                    mma1688t(acc[mi][nj], af[mi], &bf[nj >> 1][(nj & 1)*2]);
        }
        __syncthreads();
    }

    // ---- epilogue: tanh(+bias) -> split bf16 hidden ----
    const int g  = lane >> 2;
    const int cq = lane & 3;
    #pragma unroll
    for (int mi = 0; mi < 2; mi++) {
        const int row = wm*32 + mi*16 + g;
        const int gr  = r0 + row;
        #pragma unroll
        for (int nj = 0; nj < NJ; nj++) {
            const int colL = wn*NTW + nj*8 + cq*2;
            const int col  = n0 + colL;
            float b0 = sBias[colL], b1 = sBias[colL + 1];
            float v0 = tanhf(acc[mi][nj][0] + b0);
            float v1 = tanhf(acc[mi][nj][1] + b1);
            float v2 = tanhf(acc[mi][nj][2] + b0);
            float v3 = tanhf(acc[mi][nj][3] + b1);
            uint32_t hi, lo;
            splitp(v0, v1, hi, lo);
            g_hidh[(size_t)gr*128 + (col >> 1)] = hi;
            g_hidl[(size_t)gr*128 + (col >> 1)] = lo;
            splitp(v2, v3, hi, lo);
            g_hidh[(size_t)(gr + 8)*128 + (col >> 1)] = hi;
            g_hidl[(size_t)(gr + 8)*128 + (col >> 1)] = lo;
        }
    }
}

// =====================================================================
// Layer-2 GEMM (split bf16, 3-pass exact): C[128 x 64] = hid @ w2^T,
// fp32 out + means (+ X2 tf32 feed for EPI==1). KC=64 chunks, 2-stage.
// Hoisted loader addressing.
// =====================================================================
template<int EPI, int BSRC>
__global__ void __launch_bounds__(256)
gemm_l2_kernel(const float* __restrict__ bias, float* __restrict__ outF)
{
    constexpr int MT = 128, K = 256, NT = 64;
    constexpr int KP    = K / 2;
    constexpr int NC    = K / 64;
    constexpr int ABYT  = MT * 256;
    constexpr int STAGE = ABYT + NT * 256;
    constexpr int WM    = 4, WN = 2, NTW = 32, NJ = 4, NPF = 2;

    extern __shared__ unsigned char smx[];
    float* sBias  = (float*)(smx + 2*STAGE);
    float* colsum = sBias + NT;

    const uint32_t* Ahi = g_hidh;
    const uint32_t* Alo = g_hidl;
    const uint32_t* Bhi = (BSRC == 0) ? g_w2sh : g_w2mh;
    const uint32_t* Blo = (BSRC == 0) ? g_w2sl : g_w2ml;

    const int tid  = threadIdx.x;
    const int lane = tid & 31;
    const int wid  = tid >> 5;
    const int wm   = wid % WM;
    const int wn   = wid / WM;
    const int r0   = blockIdx.y * MT;
    const uint32_t sb = smem_to_u32(smx);

    // hoisted loader state
    const int lr  = tid >> 3;
    const int lg  = tid & 7;
    const uint32_t dA0 = (uint32_t)((lr << 7) + ((lg ^ (lr & 7)) << 4));
    const uint32_t* gAh = Ahi + (size_t)(r0 + lr)*KP + lg*4;
    const uint32_t* gAl = Alo + (size_t)(r0 + lr)*KP + lg*4;
    const uint32_t* gBh = Bhi + (size_t)lr*KP + lg*4;
    const uint32_t* gBl = Blo + (size_t)lr*KP + lg*4;

    auto load_stage = [&](int s, int chunk) {
        const uint32_t base = sb + s*STAGE;
        const int co = chunk * 32;
        #pragma unroll
        for (int i = 0; i < 4; i++) {          // A: 4 iters (MT=128)
            uint32_t d = base + dA0 + i*4096;
            CP16(d,            gAh + (size_t)i*32*KP + co);
            CP16(d + MT*128,   gAl + (size_t)i*32*KP + co);
        }
        #pragma unroll
        for (int i = 0; i < 2; i++) {          // B: 2 iters (NT=64)
            uint32_t d = base + ABYT + dA0 + i*4096;
            CP16(d,            gBh + (size_t)i*32*KP + co);
            CP16(d + NT*128,   gBl + (size_t)i*32*KP + co);
        }
    };

    load_stage(0, 0);
    CP_COMMIT();
    for (int t = tid; t < NT; t += 256) sBias[t] = bias[t];

    const int a_r = wm*32 + ((lane >> 3) & 1)*8 + (lane & 7);
    const int a_k = (lane >> 4) * 8;
    const int b_n = wn*NTW + (lane >> 4)*8 + (lane & 7);
    const int b_k = ((lane >> 3) & 1) * 8;

    float acc[2][NJ][4];
    #pragma unroll
    for (int mi = 0; mi < 2; mi++)
        #pragma unroll
        for (int nj = 0; nj < NJ; nj++)
            #pragma unroll
            for (int q = 0; q < 4; q++) acc[mi][nj][q] = 0.f;

    #pragma unroll 1
    for (int c = 0; c < NC; c++) {
        if (c + 1 < NC) load_stage((c + 1) & 1, c + 1);
        CP_COMMIT();
        CP_WAIT1();
        __syncthreads();

        const uint32_t st = sb + (c & 1)*STAGE;
        #pragma unroll
        for (int ks = 0; ks < 4; ks++) {
            const int k0 = ks * 16;
            uint32_t ah[2][4], al[2][4], bh[NPF][4], bl[NPF][4];
            #pragma unroll
            for (int mi = 0; mi < 2; mi++) {
                uint32_t o = coff(a_r + mi*16, k0 + a_k);
                ldsm4(ah[mi], st + o);
                ldsm4(al[mi], st + MT*128 + o);
            }
            #pragma unroll
            for (int np = 0; np < NPF; np++) {
                uint32_t o = coff(b_n + np*16, k0 + b_k);
                ldsm4(bh[np], st + ABYT + o);
                ldsm4(bl[np], st + ABYT + NT*128 + o);
            }
            #pragma unroll
            for (int mi = 0; mi < 2; mi++)
                #pragma unroll
                for (int nj = 0; nj < NJ; nj++) {
                    const uint32_t* bph = &bh[nj >> 1][(nj & 1)*2];
                    const uint32_t* bpl = &bl[nj >> 1][(nj & 1)*2];
                    mma16816(acc[mi][nj], ah[mi], bph);
                    mma16816(acc[mi][nj], ah[mi], bpl);
                    mma16816(acc[mi][nj], al[mi], bph);
                }
        }
        __syncthreads();
    }

    // ---- epilogue: fp32 out, means, optional X2 tf32 feed ----
    const int g  = lane >> 2;
    const int cq = lane & 3;
    float pe[NJ], po[NJ];
    #pragma unroll
    for (int nj = 0; nj < NJ; nj++) { pe[nj] = 0.f; po[nj] = 0.f; }
    #pragma unroll
    for (int mi = 0; mi < 2; mi++) {
        const int row = wm*32 + mi*16 + g;
        const int gr  = r0 + row;
        #pragma unroll
        for (int nj = 0; nj < NJ; nj++) {
            const int col = wn*NTW + nj*8 + cq*2;
            float b0 = sBias[col], b1 = sBias[col + 1];
            float v0 = tanhf(acc[mi][nj][0] + b0);
            float v1 = tanhf(acc[mi][nj][1] + b1);
            float v2 = tanhf(acc[mi][nj][2] + b0);
            float v3 = tanhf(acc[mi][nj][3] + b1);
            *(float2*)(outF + (size_t)gr*64 + col)       = make_float2(v0, v1);
            *(float2*)(outF + (size_t)(gr + 8)*64 + col) = make_float2(v2, v3);
            if (EPI == 1) {
                g_x2f[(size_t)gr*128 + col]           = tf32r(v0);
                g_x2f[(size_t)gr*128 + col + 1]       = tf32r(v1);
                g_x2f[(size_t)(gr + 8)*128 + col]     = tf32r(v2);
                g_x2f[(size_t)(gr + 8)*128 + col + 1] = tf32r(v3);
            }
            pe[nj] += v0 + v2;
            po[nj] += v1 + v3;
        }
    }
    #pragma unroll
    for (int nj = 0; nj < NJ; nj++) {
        pe[nj] += __shfl_down_sync(0xffffffffu, pe[nj], 16);
        pe[nj] += __shfl_down_sync(0xffffffffu, pe[nj], 8);
        pe[nj] += __shfl_down_sync(0xffffffffu, pe[nj], 4);
        po[nj] += __shfl_down_sync(0xffffffffu, po[nj], 16);
        po[nj] += __shfl_down_sync(0xffffffffu, po[nj], 8);
        po[nj] += __shfl_down_sync(0xffffffffu, po[nj], 4);
    }
    if (lane < 4) {
        #pragma unroll
        for (int nj = 0; nj < NJ; nj++) {
            const int col = wn*NTW + nj*8 + lane*2;
            colsum[wm*64 + col]     = pe[nj];
            colsum[wm*64 + col + 1] = po[nj];
        }
    }
    __syncthreads();
    if (tid < 64) {
        float s = 0.f;
        #pragma unroll
        for (int w = 0; w < WM; w++) s += colsum[w*64 + tid];
        float m = s * (1.f / 128.f);
        if (EPI == 1) g_hmean[blockIdx.y*64 + tid]   = m;
        else          g_msgmean[blockIdx.y*64 + tid] = m;
    }
}

// =====================================================================
// K6: modulator hidden (fused) + mod_out -> W_new, decay_new
// =====================================================================
__global__ void __launch_bounds__(256)
modout_kernel(const float* __restrict__ mw1,
              const float* __restrict__ mb1,
              const float* __restrict__ mw2,
              const float* __restrict__ mb2,
              const float* __restrict__ W,
              const float* __restrict__ decay,
              const float* __restrict__ drift,
              const float* __restrict__ s1,
              const float* __restrict__ s2,
              float* __restrict__ outW,
              float* __restrict__ outD)
{
    __shared__ float sW1[PMOD_IN*64];
    __shared__ float mi[8][134];
    __shared__ float hidT[512];
    const int c   = blockIdx.y;
    const int tid = threadIdx.x;
    const int b   = tid >> 5;
    const int lane = tid & 31;

    for (int t = tid; t < PMOD_IN*64; t += 256)
        sW1[t] = mw1[(size_t)c*PMOD_IN*64 + t];

    {
        const int bc = (b << 6) | c;
        for (int i = lane; i < 64; i += 32) {
            mi[b][i]      = g_hmean[bc*PDN + i];
            mi[b][64 + i] = g_msgmean[bc*PDN + i];
        }
        float ds = 0.f;
        #pragma unroll
        for (int i = 0; i < 4; i++) ds += decay[(size_t)bc*PN + lane + i*32];
        #pragma unroll
        for (int off = 16; off; off >>= 1)
            ds += __shfl_down_sync(0xffffffffu, ds, off);
        if (lane == 0) {
            mi[b][128] = g_wstats[bc];
            mi[b][129] = ds * (1.f/PN);
            mi[b][130] = drift[bc];
            mi[b][131] = s1[b];
            mi[b][132] = s2[b];
        }
    }
    __syncthreads();

    #pragma unroll
    for (int jo = 0; jo < 2; jo++) {
        const int j = lane + jo*32;
        float acc = mb1[c*PHMOD + j];
        for (int i = 0; i < PMOD_IN; i++) acc += mi[b][i] * sW1[i*64 + j];
        hidT[j*8 + b] = tanhf(acc);
    }
    __syncthreads();

    const int o0 = (blockIdx.x * 256 + tid) * 4;
    if (o0 >= PMOD_OUT) return;

    float4 acc[8];
    const float4 bias = *(const float4*)(mb2 + (size_t)c*PMOD_OUT + o0);
    #pragma unroll
    for (int bb = 0; bb < 8; bb++) acc[bb] = bias;

    const float* wp = mw2 + (size_t)c*PHMOD*PMOD_OUT + o0;
    #pragma unroll 4
    for (int hh = 0; hh < PHMOD; hh++) {
        float4 wv = __ldcs((const float4*)(wp + (size_t)hh*PMOD_OUT));
        #pragma unroll
        for (int bb = 0; bb < 8; bb++) {
            float hv = hidT[hh*8 + bb];
            acc[bb].x += hv * wv.x;
            acc[bb].y += hv * wv.y;
            acc[bb].z += hv * wv.z;
            acc[bb].w += hv * wv.w;
        }
    }

    if (o0 < PN*PN) {
        #pragma unroll
        for (int bb = 0; bb < 8; bb++) {
            size_t idx = ((size_t)(bb*PNC + c))*(PN*PN) + o0;
            float4 wold = __ldcs((const float4*)(W + idx));
            float4 r;
            r.x = wold.x + acc[bb].x; r.y = wold.y + acc[bb].y;
            r.z = wold.z + acc[bb].z; r.w = wold.w + acc[bb].w;
            __stcs((float4*)(outW + idx), r);
        }
    } else {
        const int oo = o0 - PN*PN;
        #pragma unroll
        for (int bb = 0; bb < 8; bb++) {
            size_t idx = (size_t)(bb*PNC + c)*PN + oo;
            outD[idx+0] = decay[idx+0] + acc[bb].x;
            outD[idx+1] = decay[idx+1] + acc[bb].y;
            outD[idx+2] = decay[idx+2] + acc[bb].z;
            outD[idx+3] = decay[idx+3] + acc[bb].w;
        }
    }
}

// =====================================================================
extern "C" void kernel_launch(void* const* d_in, const int* in_sizes, int n_in,
                              void* d_out, int out_size)
{
    const float* h     = (const float*)d_in[0];
    const float* msg   = (const float*)d_in[1];
    const float* W     = (const float*)d_in[2];
    const float* decay = (const float*)d_in[3];
    const float* drift = (const float*)d_in[4];
    const float* s1    = (const float*)d_in[5];
    const float* s2    = (const float*)d_in[6];
    const float* Haug  = (const float*)d_in[7];
    const float* nid   = (const float*)d_in[8];
    const float* sw1   = (const float*)d_in[9];
    const float* sb1   = (const float*)d_in[10];
    const float* sw2   = (const float*)d_in[11];
    const float* sb2   = (const float*)d_in[12];
    const float* mw1   = (const float*)d_in[13];
    const float* mb1   = (const float*)d_in[14];
    const float* mw2   = (const float*)d_in[15];
    const float* mb2   = (const float*)d_in[16];
    const float* injW  = (const float*)d_in[17];
    const float* injB  = (const float*)d_in[18];
    const float* modw1 = (const float*)d_in[19];
    const float* modb1 = (const float*)d_in[20];
    const float* modw2 = (const float*)d_in[21];
    const float* modb2 = (const float*)d_in[22];

    float* out  = (float*)d_out;
    float* outH = out;                      // h_new
    float* outM = out + 4194304;            // msg_new
    float* outW = out + 8388608;            // W_new
    float* outD = out + 16777216;           // decay_new

    const int smem1  = (128*129 + 128*68 + 64 + 128 + 8) * 4;
    // L1 tf32 (MT=64, NT=128): 2*(8192+16384) + 1024
    const int smemT1 = 2*24576 + 1024;
    // L2 (MT=128, NT=64, 3-pass): 2*(32768+16384) + 1536
    const int smemL2 = 2*49152 + 1536;

    cudaFuncSetAttribute(recv_kernel,
        cudaFuncAttributeMaxDynamicSharedMemorySize, smem1);
    cudaFuncSetAttribute(gemm_tf32_kernel<64,192,128,0,0>,
        cudaFuncAttributeMaxDynamicSharedMemorySize, smemT1);
    cudaFuncSetAttribute(gemm_tf32_kernel<64,128,128,1,1>,
        cudaFuncAttributeMaxDynamicSharedMemorySize, smemT1);
    cudaFuncSetAttribute(gemm_l2_kernel<1,0>,
        cudaFuncAttributeMaxDynamicSharedMemorySize, smemL2);
    cudaFuncSetAttribute(gemm_l2_kernel<2,1>,
        cudaFuncAttributeMaxDynamicSharedMemorySize, smemL2);

    // K1: recv + weight prep (merged)
    recv_kernel<<<CELLS + WSPLIT_BLOCKS, 256, smem1>>>(
        W, msg, h, nid, Haug, injW, injB, sw1, sw2, mw1, mw2);

    // K2: state L1 (tf32) -> hidden
    gemm_tf32_kernel<64,192,128,0,0><<<dim3(2,1024), 256, smemT1>>>(sb1);
    // K3: state L2 (exact) -> h_new + X2[:,0:64] + h_mean
    gemm_l2_kernel<1,0><<<dim3(1,512), 256, smemL2>>>(sb2, outH);
    // K4: msg L1 (tf32) -> hidden
    gemm_tf32_kernel<64,128,128,1,1><<<dim3(2,1024), 256, smemT1>>>(mb1);
    // K5: msg L2 (exact) -> msg_new + msg_mean
    gemm_l2_kernel<2,1><<<dim3(1,512), 256, smemL2>>>(mb2, outM);

    // K6: modulator (hidden + output fused) -> W_new, decay_new
    dim3 g5((PMOD_OUT + 1023)/1024, PNC);
    modout_kernel<<<g5, 256>>>(modw1, modb1, modw2, modb2, W, decay,
                               drift, s1, s2, outW, outD);
}